// round 1
// baseline (speedup 1.0000x reference)
#include <cuda_runtime.h>
#include <cuda_bf16.h>
#include <math.h>
#include <stdint.h>

// Problem constants
#define B_ROWS 8192
#define OBS    128
#define HID    512
#define HEADS  4
#define VSZ    256
#define NU     64
#define TOPK   8
#define NOPT   16

// ---------------- device scratch (static, allocation-free) ----------------
__device__ float g_wbar[HID * VSZ];        // 512x256 head-mean of value_w
__device__ float g_weff[OBS * VSZ];        // 128x256 = pre_fc_w @ wbar
__device__ float g_wp[32 * OBS * VSZ];     // k-split partials (32 slabs)
__device__ float g_bbar[VSZ];
__device__ float g_A[NOPT];
__device__ float g_C[NOPT];
__device__ float g_E[NOPT * VSZ];

// ---------------- P1: wbar = mean over heads of value_w -------------------
__global__ void prep_wbar(const float* __restrict__ value_w) {
    int k = blockIdx.x;          // 0..511
    int v = threadIdx.x;         // 0..255
    const float* p = value_w + (size_t)k * (HEADS * VSZ) + v;
    g_wbar[k * VSZ + v] = 0.25f * (p[0] + p[VSZ] + p[2 * VSZ] + p[3 * VSZ]);
}

// ---------------- P2: bbar + per-option (A, C) via warp top-k -------------
__global__ void prep_scalars(const float* __restrict__ value_b,
                             const float* __restrict__ p_w,
                             const float* __restrict__ p_b) {
    int t = threadIdx.x;         // 512 threads
    if (t < VSZ) {
        g_bbar[t] = 0.25f * (value_b[t] + value_b[VSZ + t] +
                             value_b[2 * VSZ + t] + value_b[3 * VSZ + t]);
    }
    // one warp per option: top-8 of s_n = p_w[opt,n] + p_b[n], sum sigmoids
    int lane = t & 31;
    int w = t >> 5;              // option id 0..15
    float v0 = p_w[w * NU + lane] + p_b[lane];
    float v1 = p_w[w * NU + 32 + lane] + p_b[32 + lane];
    float ssum = 0.f;
#pragma unroll
    for (int it = 0; it < TOPK; it++) {
        float mv; int mi;
        if (v0 >= v1) { mv = v0; mi = lane; } else { mv = v1; mi = lane + 32; }
#pragma unroll
        for (int off = 16; off; off >>= 1) {
            float ov = __shfl_xor_sync(0xffffffffu, mv, off);
            int   oi = __shfl_xor_sync(0xffffffffu, mi, off);
            if (ov > mv || (ov == mv && oi < mi)) { mv = ov; mi = oi; }
        }
        ssum += 1.f / (1.f + expf(-mv));
        if (mi == lane)      v0 = -1e30f;
        else if (mi == lane + 32) v1 = -1e30f;
    }
    if (lane == 0) {
        g_A[w] = ssum * (1.f / 64.f);
        g_C[w] = (8.f - ssum) * (1.f / 64.f);
    }
}

// ---------------- P3: k-split partial GEMM  W_eff = pre_fc_w @ wbar -------
// grid (4 v-tiles, 32 k-splits of 16), block 256.
__global__ void prep_weff_partial(const float* __restrict__ pfw) {
    __shared__ float a_s[16][132];   // [kk][o] transposed pre_fc_w chunk
    __shared__ float b_s[16][64];    // [kk][v]
    int vt = blockIdx.x, ks = blockIdx.y;
    int t = threadIdx.x;

    for (int idx = t; idx < 512; idx += 256) {
        int o = idx >> 2, kq = (idx & 3) * 4;
        float4 w4 = *(const float4*)(pfw + (size_t)o * HID + ks * 16 + kq);
        a_s[kq + 0][o] = w4.x; a_s[kq + 1][o] = w4.y;
        a_s[kq + 2][o] = w4.z; a_s[kq + 3][o] = w4.w;
    }
    {
        int k = t >> 4, vq = (t & 15) * 4;
        *(float4*)&b_s[k][vq] =
            *(const float4*)(g_wbar + (size_t)(ks * 16 + k) * VSZ + vt * 64 + vq);
    }
    __syncthreads();

    int tx = t & 15, ty = t >> 4;
    float acc[8][4] = {};
#pragma unroll
    for (int kk = 0; kk < 16; kk++) {
        float4 b4 = *(float4*)&b_s[kk][tx * 4];
#pragma unroll
        for (int i = 0; i < 8; i++) {
            float a = a_s[kk][ty * 8 + i];
            acc[i][0] += a * b4.x; acc[i][1] += a * b4.y;
            acc[i][2] += a * b4.z; acc[i][3] += a * b4.w;
        }
    }
    float* dst = g_wp + (size_t)ks * (OBS * VSZ);
#pragma unroll
    for (int i = 0; i < 8; i++) {
        *(float4*)&dst[(ty * 8 + i) * VSZ + vt * 64 + tx * 4] =
            make_float4(acc[i][0], acc[i][1], acc[i][2], acc[i][3]);
    }
}

// ---------------- P4: reduce the 32 slabs ---------------------------------
__global__ void prep_weff_reduce() {
    int i = blockIdx.x * 256 + threadIdx.x;   // 128 blocks -> 32768
    float s = 0.f;
#pragma unroll
    for (int ks = 0; ks < 32; ks++) s += g_wp[ks * (OBS * VSZ) + i];
    g_weff[i] = s;
}

// ---------------- P5: E[opt][v] = A*c0_v + C*bbar_v -----------------------
// warp per v: c0_v = pre_fc_b . wbar[:,v] + bbar_v
__global__ void prep_E(const float* __restrict__ pfb) {
    int t = threadIdx.x;
    int lane = t & 31;
    int v = blockIdx.x * 8 + (t >> 5);        // 32 blocks x 8 warps = 256
    float sum = 0.f;
    for (int k = lane; k < HID; k += 32) sum += pfb[k] * g_wbar[k * VSZ + v];
#pragma unroll
    for (int off = 16; off; off >>= 1) sum += __shfl_xor_sync(0xffffffffu, sum, off);
    float bb = g_bbar[v];
    float c0 = sum + bb;
    if (lane < NOPT) g_E[lane * VSZ + v] = g_A[lane] * c0 + g_C[lane] * bb;
}

// ---------------- Main GEMM: out = (A.*x) @ W_eff + E ---------------------
// block tile 128x128, 256 threads, 8x8 microtile with packed fp32x2 FMA.
#define XS_STRIDE 68   // 64 k-chunk + 4 pad (keeps 16B align, kills bank conflicts)

#define FMA2(acc, a, b) \
    asm("fma.rn.f32x2 %0, %1, %2, %0;" : "+l"(acc) : "l"(a), "l"(b))

__global__ __launch_bounds__(256)
void main_gemm(const float* __restrict__ x, const int* __restrict__ opt,
               float* __restrict__ out) {
    extern __shared__ float sm[];
    float* xs = sm;                            // 128 rows * 68
    float* ws = sm + 128 * XS_STRIDE;          // 64 k * 128 v
    float* sA = ws + 64 * 128;                 // 128 scales
    int*   sO = (int*)(sA + 128);              // 128 option ids

    int t  = threadIdx.x;
    int cb = blockIdx.x * 128;                 // col base (0 or 128)
    int rb = blockIdx.y * 128;                 // row base

    if (t < 128) {
        int o = opt[rb + t];
        sO[t] = o;
        sA[t] = g_A[o];
    }
    __syncthreads();

    int tx = t & 15, ty = t >> 4;

    unsigned long long acc[2][4][2][2];        // [rq][i][cq][pair] packed f32x2
#pragma unroll
    for (int a0 = 0; a0 < 2; a0++)
#pragma unroll
        for (int a1 = 0; a1 < 4; a1++)
#pragma unroll
            for (int a2 = 0; a2 < 2; a2++) {
                acc[a0][a1][a2][0] = 0ull; acc[a0][a1][a2][1] = 0ull;
            }

    for (int kb = 0; kb < OBS; kb += 64) {
        // stage W_eff tile [64 k x 128 v]
#pragma unroll
        for (int i = 0; i < 8; i++) {
            int idx = t + i * 256;
            int k = idx >> 5, vq = (idx & 31) << 2;
            *(float4*)&ws[k * 128 + vq] =
                *(const float4*)(g_weff + (size_t)(kb + k) * VSZ + cb + vq);
        }
        // stage x tile [128 r x 64 k], pre-scaled by A[opt]
#pragma unroll
        for (int i = 0; i < 8; i++) {
            int idx = t + i * 256;
            int r = idx >> 4, kq = (idx & 15) << 2;
            float4 v4 = *(const float4*)(x + (size_t)(rb + r) * OBS + kb + kq);
            float a = sA[r];
            v4.x *= a; v4.y *= a; v4.z *= a; v4.w *= a;
            *(float4*)&xs[r * XS_STRIDE + kq] = v4;
        }
        __syncthreads();

#pragma unroll 4
        for (int k = 0; k < 64; k++) {
            ulonglong2 b0 = *(const ulonglong2*)&ws[k * 128 + tx * 4];
            ulonglong2 b1 = *(const ulonglong2*)&ws[k * 128 + 64 + tx * 4];
#pragma unroll
            for (int rq = 0; rq < 2; rq++) {
#pragma unroll
                for (int i = 0; i < 4; i++) {
                    float a = xs[(rq * 64 + ty * 4 + i) * XS_STRIDE + k];
                    unsigned long long aa;
                    asm("mov.b64 %0, {%1, %1};" : "=l"(aa) : "r"(__float_as_uint(a)));
                    FMA2(acc[rq][i][0][0], aa, b0.x);
                    FMA2(acc[rq][i][0][1], aa, b0.y);
                    FMA2(acc[rq][i][1][0], aa, b1.x);
                    FMA2(acc[rq][i][1][1], aa, b1.y);
                }
            }
        }
        __syncthreads();
    }

    // epilogue: out = acc + E[opt][v]
#pragma unroll
    for (int rq = 0; rq < 2; rq++) {
#pragma unroll
        for (int i = 0; i < 4; i++) {
            int rl = rq * 64 + ty * 4 + i;
            int row = rb + rl;
            const float* Ep = g_E + (size_t)sO[rl] * VSZ + cb;
#pragma unroll
            for (int cq = 0; cq < 2; cq++) {
                int c = cq * 64 + tx * 4;
                float4 e = *(const float4*)(Ep + c);
                unsigned int u0, u1, u2, u3;
                asm("mov.b64 {%0,%1}, %2;" : "=r"(u0), "=r"(u1) : "l"(acc[rq][i][cq][0]));
                asm("mov.b64 {%0,%1}, %2;" : "=r"(u2), "=r"(u3) : "l"(acc[rq][i][cq][1]));
                float4 o4 = make_float4(__uint_as_float(u0) + e.x,
                                        __uint_as_float(u1) + e.y,
                                        __uint_as_float(u2) + e.z,
                                        __uint_as_float(u3) + e.w);
                *(float4*)(out + (size_t)row * VSZ + cb + c) = o4;
            }
        }
    }
}

// ---------------- launch ---------------------------------------------------
extern "C" void kernel_launch(void* const* d_in, const int* in_sizes, int n_in,
                              void* d_out, int out_size) {
    (void)in_sizes; (void)n_in; (void)out_size;
    const float* x        = (const float*)d_in[0];
    const int*   option   = (const int*)  d_in[1];
    const float* pre_fc_w = (const float*)d_in[2];
    const float* pre_fc_b = (const float*)d_in[3];
    const float* value_w  = (const float*)d_in[4];
    const float* value_b  = (const float*)d_in[5];
    const float* p_w      = (const float*)d_in[6];
    const float* p_b      = (const float*)d_in[7];
    float* out = (float*)d_out;

    prep_wbar<<<HID, VSZ>>>(value_w);
    prep_scalars<<<1, 512>>>(value_b, p_w, p_b);
    prep_weff_partial<<<dim3(4, 32), 256>>>(pre_fc_w);
    prep_weff_reduce<<<128, 256>>>();
    prep_E<<<32, 256>>>(pre_fc_b);

    size_t smem = (128 * XS_STRIDE + 64 * 128 + 128) * sizeof(float) + 128 * sizeof(int);
    cudaFuncSetAttribute(main_gemm, cudaFuncAttributeMaxDynamicSharedMemorySize, (int)smem);
    main_gemm<<<dim3(2, 64), 256, smem>>>(x, option, out);
}

// round 2
// speedup vs baseline: 1.0617x; 1.0617x over previous
#include <cuda_runtime.h>
#include <cuda_bf16.h>
#include <math.h>
#include <stdint.h>

#define B_ROWS 8192
#define OBS    128
#define HID    512
#define HEADS  4
#define VSZ    256
#define NU     64
#define TOPK   8
#define NOPT   16

// ---------------- device scratch (static, allocation-free) ----------------
__device__ float g_weff[OBS * VSZ];   // 128x256 = pre_fc_w @ wbar
__device__ float g_c0[VSZ];           // pre_fc_b . wbar[:,v] + bbar[v]
__device__ float g_bb[VSZ];           // head-mean of value_b
__device__ float g_A[NOPT];
__device__ float g_C[NOPT];

// ===================== K1: fused prep (65 blocks) ==========================
// blocks 0..63: 4-column slice of wbar (local), W_eff cols, c0, bbar
// block 64: per-option top-k scalars A, C
__global__ __launch_bounds__(256)
void prep_kernel(const float* __restrict__ value_w,
                 const float* __restrict__ value_b,
                 const float* __restrict__ pfw,
                 const float* __restrict__ pfb,
                 const float* __restrict__ p_w,
                 const float* __restrict__ p_b) {
    int blk = blockIdx.x;
    int t = threadIdx.x;

    if (blk == 64) {
        // ---- scalars: 8 warps, warp w handles options w and w+8 ----
        int lane = t & 31, w = t >> 5;
        for (int o = w; o < NOPT; o += 8) {
            float v0 = p_w[o * NU + lane] + p_b[lane];
            float v1 = p_w[o * NU + 32 + lane] + p_b[32 + lane];
            float ssum = 0.f;
#pragma unroll
            for (int it = 0; it < TOPK; it++) {
                float mv; int mi;
                if (v0 >= v1) { mv = v0; mi = lane; } else { mv = v1; mi = lane + 32; }
#pragma unroll
                for (int off = 16; off; off >>= 1) {
                    float ov = __shfl_xor_sync(0xffffffffu, mv, off);
                    int   oi = __shfl_xor_sync(0xffffffffu, mi, off);
                    if (ov > mv || (ov == mv && oi < mi)) { mv = ov; mi = oi; }
                }
                ssum += 1.f / (1.f + expf(-mv));
                if (mi == lane)           v0 = -1e30f;
                else if (mi == lane + 32) v1 = -1e30f;
            }
            if (lane == 0) {
                g_A[o] = ssum * (1.f / 64.f);
                g_C[o] = (8.f - ssum) * (1.f / 64.f);
            }
        }
        return;
    }

    __shared__ float wbT[4][HID];    // transposed wbar slice: [col j][k]
    __shared__ float red[256];       // c0 partials
    int C = blk * 4;                 // this block's 4 output columns

    // ---- Phase A: wbar slice = 0.25 * sum over heads ----
#pragma unroll
    for (int rr = 0; rr < 2; rr++) {
        int r = t * 2 + rr;          // 0..511
        const float* p = value_w + (size_t)r * (HEADS * VSZ) + C;
        float4 s0 = *(const float4*)(p);
        float4 s1 = *(const float4*)(p + VSZ);
        float4 s2 = *(const float4*)(p + 2 * VSZ);
        float4 s3 = *(const float4*)(p + 3 * VSZ);
        wbT[0][r] = 0.25f * (s0.x + s1.x + s2.x + s3.x);
        wbT[1][r] = 0.25f * (s0.y + s1.y + s2.y + s3.y);
        wbT[2][r] = 0.25f * (s0.z + s1.z + s2.z + s3.z);
        wbT[3][r] = 0.25f * (s0.w + s1.w + s2.w + s3.w);
    }
    __syncthreads();

    int j  = t & 3;                  // column within slice
    int rg = t >> 2;                 // 0..63

    // ---- c0 partials: k = rg*8 .. rg*8+7 for column j ----
    {
        float s = 0.f;
#pragma unroll
        for (int i = 0; i < 8; i++) {
            int k = rg * 8 + i;
            s += pfb[k] * wbT[j][k];
        }
        red[t] = s;
    }

    // ---- Phase B: W_eff rows (2 per thread), full K=512 ----
    int r0 = rg * 2, r1 = r0 + 1;
    const float* a0p = pfw + (size_t)r0 * HID;
    const float* a1p = pfw + (size_t)r1 * HID;
    float acc0 = 0.f, acc1 = 0.f;
#pragma unroll 8
    for (int k = 0; k < HID; k += 4) {
        float4 a0 = *(const float4*)(a0p + k);
        float4 a1 = *(const float4*)(a1p + k);
        float4 b  = *(const float4*)&wbT[j][k];
        acc0 += a0.x * b.x + a0.y * b.y + a0.z * b.z + a0.w * b.w;
        acc1 += a1.x * b.x + a1.y * b.y + a1.z * b.z + a1.w * b.w;
    }
    g_weff[r0 * VSZ + C + j] = acc0;
    g_weff[r1 * VSZ + C + j] = acc1;

    __syncthreads();
    if (t < 4) {
        float s = 0.f;
#pragma unroll
        for (int m = 0; m < 64; m++) s += red[t + 4 * m];
        float bb = 0.25f * (value_b[C + t] + value_b[VSZ + C + t] +
                            value_b[2 * VSZ + C + t] + value_b[3 * VSZ + C + t]);
        g_bb[C + t] = bb;
        g_c0[C + t] = s + bb;        // pre_fc_b . wbar + bbar
    }
}

// ===================== K2: main GEMM ======================================
// out[b,v] = A[opt_b] * (x_b . W_eff[:,v] + c0[v]) + C[opt_b] * bb[v]
// 128 blocks x 256 threads; tile 64 rows x 256 cols, full K=128 staged once.
#define KX 132   // 128 + 4 pad (16B-aligned, conflict-free)

#define FMA2(acc, a, b) \
    asm("fma.rn.f32x2 %0, %1, %2, %0;" : "+l"(acc) : "l"(a), "l"(b))

__global__ __launch_bounds__(256, 1)
void main_gemm(const float* __restrict__ x, const int* __restrict__ opt,
               float* __restrict__ out) {
    extern __shared__ float sm[];
    float* ws  = sm;                  // 128 k x 256 v  (matches g_weff layout)
    float* xs  = ws + OBS * VSZ;      // 64 rows x KX
    float* sA  = xs + 64 * KX;        // 64
    float* sC  = sA + 64;             // 64
    float* sc0 = sC + 64;             // 256
    float* sbb = sc0 + VSZ;           // 256

    int t  = threadIdx.x;
    int rb = blockIdx.x * 64;

    // ---- stage W_eff (straight copy, layouts identical) ----
#pragma unroll
    for (int i = 0; i < 32; i++) {
        int idx = t + i * 256;        // 8192 float4
        *(float4*)&ws[idx * 4] = *(const float4*)(g_weff + idx * 4);
    }
    // ---- stage x tile ----
#pragma unroll
    for (int i = 0; i < 8; i++) {
        int idx = t + i * 256;        // 2048 float4
        int r = idx >> 5, kq = (idx & 31) << 2;
        *(float4*)&xs[r * KX + kq] = *(const float4*)(x + (size_t)(rb + r) * OBS + kq);
    }
    // ---- stage per-row scales and per-col constants ----
    if (t < 64) {
        int o = opt[rb + t];
        sA[t] = g_A[o];
        sC[t] = g_C[o];
    }
    sc0[t] = g_c0[t];
    sbb[t] = g_bb[t];
    __syncthreads();

    int tx = t & 15, ty = t >> 4;

    unsigned long long acc[4][4][2];  // [row i][col quad q][pair]
#pragma unroll
    for (int i = 0; i < 4; i++)
#pragma unroll
        for (int q = 0; q < 4; q++) { acc[i][q][0] = 0ull; acc[i][q][1] = 0ull; }

#pragma unroll 4
    for (int k = 0; k < OBS; k++) {
        ulonglong2 w0 = *(const ulonglong2*)&ws[k * VSZ +   0 + tx * 4];
        ulonglong2 w1 = *(const ulonglong2*)&ws[k * VSZ +  64 + tx * 4];
        ulonglong2 w2 = *(const ulonglong2*)&ws[k * VSZ + 128 + tx * 4];
        ulonglong2 w3 = *(const ulonglong2*)&ws[k * VSZ + 192 + tx * 4];
#pragma unroll
        for (int i = 0; i < 4; i++) {
            float a = xs[(ty * 4 + i) * KX + k];
            unsigned long long aa;
            asm("mov.b64 %0, {%1, %1};" : "=l"(aa) : "r"(__float_as_uint(a)));
            FMA2(acc[i][0][0], aa, w0.x); FMA2(acc[i][0][1], aa, w0.y);
            FMA2(acc[i][1][0], aa, w1.x); FMA2(acc[i][1][1], aa, w1.y);
            FMA2(acc[i][2][0], aa, w2.x); FMA2(acc[i][2][1], aa, w2.y);
            FMA2(acc[i][3][0], aa, w3.x); FMA2(acc[i][3][1], aa, w3.y);
        }
    }

    // ---- epilogue ----
#pragma unroll
    for (int i = 0; i < 4; i++) {
        int rl  = ty * 4 + i;
        int row = rb + rl;
        float Ar = sA[rl], Cr = sC[rl];
#pragma unroll
        for (int q = 0; q < 4; q++) {
            int c = q * 64 + tx * 4;
            unsigned int u0, u1, u2, u3;
            asm("mov.b64 {%0,%1}, %2;" : "=r"(u0), "=r"(u1) : "l"(acc[i][q][0]));
            asm("mov.b64 {%0,%1}, %2;" : "=r"(u2), "=r"(u3) : "l"(acc[i][q][1]));
            float4 o4;
            o4.x = Ar * (__uint_as_float(u0) + sc0[c + 0]) + Cr * sbb[c + 0];
            o4.y = Ar * (__uint_as_float(u1) + sc0[c + 1]) + Cr * sbb[c + 1];
            o4.z = Ar * (__uint_as_float(u2) + sc0[c + 2]) + Cr * sbb[c + 2];
            o4.w = Ar * (__uint_as_float(u3) + sc0[c + 3]) + Cr * sbb[c + 3];
            *(float4*)(out + (size_t)row * VSZ + c) = o4;
        }
    }
}

// ---------------- launch ---------------------------------------------------
extern "C" void kernel_launch(void* const* d_in, const int* in_sizes, int n_in,
                              void* d_out, int out_size) {
    (void)in_sizes; (void)n_in; (void)out_size;
    const float* x        = (const float*)d_in[0];
    const int*   option   = (const int*)  d_in[1];
    const float* pre_fc_w = (const float*)d_in[2];
    const float* pre_fc_b = (const float*)d_in[3];
    const float* value_w  = (const float*)d_in[4];
    const float* value_b  = (const float*)d_in[5];
    const float* p_w      = (const float*)d_in[6];
    const float* p_b      = (const float*)d_in[7];
    float* out = (float*)d_out;

    prep_kernel<<<65, 256>>>(value_w, value_b, pre_fc_w, pre_fc_b, p_w, p_b);

    size_t smem = (OBS * VSZ + 64 * KX + 64 + 64 + VSZ + VSZ) * sizeof(float);
    cudaFuncSetAttribute(main_gemm, cudaFuncAttributeMaxDynamicSharedMemorySize, (int)smem);
    main_gemm<<<128, 256, smem>>>(x, option, out);
}